// round 7
// baseline (speedup 1.0000x reference)
#include <cuda_runtime.h>
#include <cuda_bf16.h>
#include <stdint.h>

#define N_NODES 100000
#define NE      1600000
#define IN_DIM  256
#define HID     128
#define SCAN_B  ((N_NODES + 1023) / 1024)   // 98 scan blocks

// ---------------- scratch (static device globals; no allocation) ------------
__device__ int      d_src32[NE];
__device__ int      d_dst32[NE];
__device__ int      d_srcs[NE];
__device__ int      d_cnt[N_NODES];
__device__ int      d_rowptr[N_NODES];
__device__ int      d_cursor[N_NODES];
__device__ float    d_dinv[N_NODES];
__device__ int      d_bsum[SCAN_B];
__device__ int      d_boff[SCAN_B];
__device__ float    d_h[(size_t)N_NODES * HID];
__device__ float    d_t[(size_t)N_NODES * HID];
__device__ unsigned d_whi[128 * 128];   // split W, [n][kp] permuted, K<=256
__device__ unsigned d_wlo[128 * 128];
__device__ int      g_is64;

// ---------------- helpers -----------------------------------------------------
__device__ __forceinline__ unsigned pack_bf16x2(float k_even, float k_odd) {
    unsigned r;
    asm("cvt.rn.bf16x2.f32 %0, %1, %2;" : "=r"(r) : "f"(k_odd), "f"(k_even));
    return r;
}
__device__ __forceinline__ void mma_bf16(float* c, unsigned a0, unsigned a1,
                                         unsigned a2, unsigned a3,
                                         unsigned b0, unsigned b1) {
    asm("mma.sync.aligned.m16n8k16.row.col.f32.bf16.bf16.f32 "
        "{%0,%1,%2,%3}, {%4,%5,%6,%7}, {%8,%9}, {%0,%1,%2,%3};"
        : "+f"(c[0]), "+f"(c[1]), "+f"(c[2]), "+f"(c[3])
        : "r"(a0), "r"(a1), "r"(a2), "r"(a3), "r"(b0), "r"(b1));
}
// fragment permutation: pair j within group of 8 -> storage position
__device__ __forceinline__ int perm_pos(int p /*0..15*/) {
    int kk = p >> 3, j = p & 7;
    return kk * 8 + ((j < 4) ? (2 * j) : (2 * (j - 4) + 1));
}

// ---------------- edge dtype detection + conversion + count ------------------
__global__ void k_detect(const int* __restrict__ w) {
    int ok = 1;
    for (int i = 0; i < 64; i++) {
        if (w[2 * i + 1] != 0) { ok = 0; break; }
    }
    g_is64 = ok;
}

__global__ void k_zero_cnt() {
    int i = blockIdx.x * blockDim.x + threadIdx.x;
    if (i < N_NODES) d_cnt[i] = 0;
}

__global__ void k_convert_count(const void* __restrict__ ei) {
    int e = blockIdx.x * blockDim.x + threadIdx.x;
    if (e >= NE) return;
    int s, d;
    if (g_is64) {
        const long long* p = (const long long*)ei;
        s = (int)p[e];
        d = (int)p[e + NE];
    } else {
        const int* p = (const int*)ei;
        s = p[e];
        d = p[e + NE];
    }
    d_src32[e] = s;
    d_dst32[e] = d;
    atomicAdd(&d_cnt[d], 1);
}

// ---------------- parallel 3-phase scan --------------------------------------
__global__ void __launch_bounds__(1024) k_scan1() {
    __shared__ int wsum[32];
    const int tid  = threadIdx.x;
    const int lane = tid & 31;
    const int w    = tid >> 5;
    const int gid  = blockIdx.x * 1024 + tid;

    int c = (gid < N_NODES) ? d_cnt[gid] : 0;
    int v = c;
#pragma unroll
    for (int o = 1; o < 32; o <<= 1) {
        int t = __shfl_up_sync(0xFFFFFFFFu, v, o);
        if (lane >= o) v += t;
    }
    if (lane == 31) wsum[w] = v;
    __syncthreads();
    if (w == 0) {
        int s = wsum[lane];
#pragma unroll
        for (int o = 1; o < 32; o <<= 1) {
            int t = __shfl_up_sync(0xFFFFFFFFu, s, o);
            if (lane >= o) s += t;
        }
        wsum[lane] = s;
    }
    __syncthreads();
    int excl = v - c + (w ? wsum[w - 1] : 0);
    if (gid < N_NODES) d_rowptr[gid] = excl;
    if (tid == 1023) d_bsum[blockIdx.x] = wsum[31];
}

__global__ void k_scan2() {
    __shared__ int s[128];
    const int t = threadIdx.x;
    s[t] = (t < SCAN_B) ? d_bsum[t] : 0;
    __syncthreads();
    for (int o = 1; o < 128; o <<= 1) {
        int v = (t >= o) ? s[t - o] : 0;
        __syncthreads();
        s[t] += v;
        __syncthreads();
    }
    if (t < SCAN_B) d_boff[t] = (t ? s[t - 1] : 0);
}

__global__ void k_scan3() {
    const int gid = blockIdx.x * blockDim.x + threadIdx.x;
    if (gid >= N_NODES) return;
    int rp = d_rowptr[gid] + d_boff[gid >> 10];
    d_rowptr[gid] = rp;
    d_cursor[gid] = rp;
    d_dinv[gid] = rsqrtf((float)(d_cnt[gid] + 1));  // +1 = self loop
}

__global__ void k_fill() {
    int e = blockIdx.x * blockDim.x + threadIdx.x;
    if (e >= NE) return;
    int dd = d_dst32[e];
    int pos = atomicAdd(&d_cursor[dd], 1);
    d_srcs[pos] = d_src32[e];
}

// ---------------- W pre-split -------------------------------------------------
// d_whi/d_wlo[n][K/2], [n][kp] transposed, fragment permutation baked in.
template <int K>
__global__ void k_wsplit(const float* __restrict__ W) {
    const int tot = 128 * (K / 2);
    int i = blockIdx.x * blockDim.x + threadIdx.x;
    if (i >= tot) return;
    int n  = i / (K / 2);
    int op = i % (K / 2);                 // output position within row
    int chunk = op >> 4, pos = op & 15;
    int kk = pos >> 3, q = pos & 7;
    int j  = (q & 1) ? ((q >> 1) + 4) : (q >> 1);   // inverse permutation
    int kp = chunk * 16 + kk * 8 + j;
    float w0 = W[(size_t)(2 * kp)     * 128 + n];
    float w1 = W[(size_t)(2 * kp + 1) * 128 + n];
    float h0 = __bfloat162float(__float2bfloat16(w0));
    float h1 = __bfloat162float(__float2bfloat16(w1));
    d_whi[i] = pack_bf16x2(h0, h1);
    d_wlo[i] = pack_bf16x2(w0 - h0, w1 - h1);
}

// ---------------- tensor-core GEMM ------------------------------------------
// C[M,128] = act(A[M,K] @ W + b), split-bf16 3-term compensation.
// 256 thr / 8 warps, tile 128x128, BK=32. smem rows stride 24 words
// (conflict-free for the permuted LDS.64 fragment loads).
#define SROW 24
template <int K, bool RELU, bool BIAS>
__global__ void __launch_bounds__(256) k_gemm_tc(const float* __restrict__ A,
                                                 const float* __restrict__ bias,
                                                 float* __restrict__ C, int M) {
    __shared__ unsigned sAhi[128][SROW];
    __shared__ unsigned sAlo[128][SROW];
    __shared__ unsigned sWhi[128][SROW];
    __shared__ unsigned sWlo[128][SROW];

    const int tid   = threadIdx.x;
    const int warp  = tid >> 5;
    const int lane  = tid & 31;
    const int g     = lane >> 2;
    const int tig   = lane & 3;
    const int mbase = warp * 16;
    const int row0  = blockIdx.x * 128;
    constexpr int NCHUNK = K / 32;

    // A-fill decomposition (constant per thread)
    const int a_r0 = tid >> 3;            // + i*32
    const int a_c4 = tid & 7;             // float4 index -> pairs 2c4, 2c4+1
    const int apos0 = perm_pos(2 * a_c4);
    const int apos1 = perm_pos(2 * a_c4 + 1);
    // W-fill: thread copies uint4 #tid and #(tid+256) of 512
    const int w_n0 = tid >> 2,          w_p0 = tid & 3;
    const int w_n1 = (tid + 256) >> 2,  w_p1 = (tid + 256) & 3;

    float acc[16][4];
#pragma unroll
    for (int nb = 0; nb < 16; nb++)
#pragma unroll
        for (int i = 0; i < 4; i++) acc[nb][i] = 0.f;

    // ---- prologue: prefetch chunk 0 -----------------------------------------
    float4 av[4];
    uint4  wh[2], wl[2];
    {
#pragma unroll
        for (int i = 0; i < 4; i++) {
            int grow = row0 + a_r0 + i * 32;
            av[i] = (grow < M) ? *(const float4*)(A + (size_t)grow * K + a_c4 * 4)
                               : make_float4(0.f, 0.f, 0.f, 0.f);
        }
        wh[0] = *(const uint4*)(d_whi + w_n0 * (K / 2) + w_p0 * 4);
        wh[1] = *(const uint4*)(d_whi + w_n1 * (K / 2) + w_p1 * 4);
        wl[0] = *(const uint4*)(d_wlo + w_n0 * (K / 2) + w_p0 * 4);
        wl[1] = *(const uint4*)(d_wlo + w_n1 * (K / 2) + w_p1 * 4);
    }

    for (int ch = 0; ch < NCHUNK; ch++) {
        // ---- store prefetched tile to smem ----------------------------------
#pragma unroll
        for (int i = 0; i < 4; i++) {
            float4 v = av[i];
            int r = a_r0 + i * 32;
            float hx = __bfloat162float(__float2bfloat16(v.x));
            float hy = __bfloat162float(__float2bfloat16(v.y));
            float hz = __bfloat162float(__float2bfloat16(v.z));
            float hw = __bfloat162float(__float2bfloat16(v.w));
            sAhi[r][apos0] = pack_bf16x2(hx, hy);
            sAhi[r][apos1] = pack_bf16x2(hz, hw);
            sAlo[r][apos0] = pack_bf16x2(v.x - hx, v.y - hy);
            sAlo[r][apos1] = pack_bf16x2(v.z - hz, v.w - hw);
        }
        *(uint4*)(&sWhi[w_n0][w_p0 * 4]) = wh[0];
        *(uint4*)(&sWhi[w_n1][w_p1 * 4]) = wh[1];
        *(uint4*)(&sWlo[w_n0][w_p0 * 4]) = wl[0];
        *(uint4*)(&sWlo[w_n1][w_p1 * 4]) = wl[1];
        __syncthreads();

        // ---- prefetch next chunk while computing ----------------------------
        if (ch + 1 < NCHUNK) {
            int kc = (ch + 1) * 32;
#pragma unroll
            for (int i = 0; i < 4; i++) {
                int grow = row0 + a_r0 + i * 32;
                av[i] = (grow < M)
                    ? *(const float4*)(A + (size_t)grow * K + kc + a_c4 * 4)
                    : make_float4(0.f, 0.f, 0.f, 0.f);
            }
            int wo = (ch + 1) * 16;
            wh[0] = *(const uint4*)(d_whi + w_n0 * (K / 2) + wo + w_p0 * 4);
            wh[1] = *(const uint4*)(d_whi + w_n1 * (K / 2) + wo + w_p1 * 4);
            wl[0] = *(const uint4*)(d_wlo + w_n0 * (K / 2) + wo + w_p0 * 4);
            wl[1] = *(const uint4*)(d_wlo + w_n1 * (K / 2) + wo + w_p1 * 4);
        }

        // ---- MMAs -----------------------------------------------------------
#pragma unroll
        for (int kk = 0; kk < 2; kk++) {
            const int co = kk * 8 + 2 * tig;   // word offset within row
            uint2 ahA = *(const uint2*)(&sAhi[mbase + g][co]);      // (a0,a2)
            uint2 ahB = *(const uint2*)(&sAhi[mbase + g + 8][co]);  // (a1,a3)
            uint2 alA = *(const uint2*)(&sAlo[mbase + g][co]);
            uint2 alB = *(const uint2*)(&sAlo[mbase + g + 8][co]);
#pragma unroll
            for (int nb = 0; nb < 16; nb++) {
                uint2 bh = *(const uint2*)(&sWhi[nb * 8 + g][co]);  // (b0,b1)
                uint2 bl = *(const uint2*)(&sWlo[nb * 8 + g][co]);
                mma_bf16(acc[nb], ahA.x, ahB.x, ahA.y, ahB.y, bh.x, bh.y);
                mma_bf16(acc[nb], ahA.x, ahB.x, ahA.y, ahB.y, bl.x, bl.y);
                mma_bf16(acc[nb], alA.x, alB.x, alA.y, alB.y, bh.x, bh.y);
            }
        }
        __syncthreads();
    }

    // ---- epilogue -----------------------------------------------------------
    const int r0 = row0 + mbase + g;
    const int r1 = r0 + 8;
#pragma unroll
    for (int nb = 0; nb < 16; nb++) {
        int col = nb * 8 + tig * 2;
        float b0 = 0.f, b1 = 0.f;
        if (BIAS) { b0 = bias[col]; b1 = bias[col + 1]; }
        float2 v0, v1;
        v0.x = acc[nb][0] + b0; v0.y = acc[nb][1] + b1;
        v1.x = acc[nb][2] + b0; v1.y = acc[nb][3] + b1;
        if (RELU) {
            v0.x = fmaxf(v0.x, 0.f); v0.y = fmaxf(v0.y, 0.f);
            v1.x = fmaxf(v1.x, 0.f); v1.y = fmaxf(v1.y, 0.f);
        }
        if (r0 < M) *(float2*)(C + (size_t)r0 * 128 + col) = v0;
        if (r1 < M) *(float2*)(C + (size_t)r1 * 128 + col) = v1;
    }
}

// ---------------- GCN aggregate: warp per destination node, 4-way unroll ----
__global__ void __launch_bounds__(256) k_aggregate(const float* __restrict__ t,
                                                   const float* __restrict__ b,
                                                   float* __restrict__ hout) {
    const int wid  = (blockIdx.x * blockDim.x + threadIdx.x) >> 5;
    const int lane = threadIdx.x & 31;
    if (wid >= N_NODES) return;
    const int d = wid;

    const float4* t4 = (const float4*)t;
    const float dd = d_dinv[d];

    float4 a0 = t4[d * 32 + lane];   // self term
    a0.x *= dd; a0.y *= dd; a0.z *= dd; a0.w *= dd;
    float4 a1 = make_float4(0.f, 0.f, 0.f, 0.f);
    float4 a2 = make_float4(0.f, 0.f, 0.f, 0.f);
    float4 a3 = make_float4(0.f, 0.f, 0.f, 0.f);

    const int beg = d_rowptr[d];
    const int num = d_cnt[d];
    int j = 0;
    for (; j + 4 <= num; j += 4) {
        int s0 = d_srcs[beg + j];
        int s1 = d_srcs[beg + j + 1];
        int s2 = d_srcs[beg + j + 2];
        int s3 = d_srcs[beg + j + 3];
        float ds0 = d_dinv[s0], ds1 = d_dinv[s1];
        float ds2 = d_dinv[s2], ds3 = d_dinv[s3];
        float4 v0 = t4[s0 * 32 + lane];
        float4 v1 = t4[s1 * 32 + lane];
        float4 v2 = t4[s2 * 32 + lane];
        float4 v3 = t4[s3 * 32 + lane];
        a0.x += v0.x * ds0; a0.y += v0.y * ds0; a0.z += v0.z * ds0; a0.w += v0.w * ds0;
        a1.x += v1.x * ds1; a1.y += v1.y * ds1; a1.z += v1.z * ds1; a1.w += v1.w * ds1;
        a2.x += v2.x * ds2; a2.y += v2.y * ds2; a2.z += v2.z * ds2; a2.w += v2.w * ds2;
        a3.x += v3.x * ds3; a3.y += v3.y * ds3; a3.z += v3.z * ds3; a3.w += v3.w * ds3;
    }
    for (; j < num; j++) {
        int s = d_srcs[beg + j];
        float ds = d_dinv[s];
        float4 v = t4[s * 32 + lane];
        a0.x += v.x * ds; a0.y += v.y * ds; a0.z += v.z * ds; a0.w += v.w * ds;
    }

    float4 bv = ((const float4*)b)[lane];
    float4 o;
    o.x = (a0.x + a1.x + a2.x + a3.x) * dd + bv.x;
    o.y = (a0.y + a1.y + a2.y + a3.y) * dd + bv.y;
    o.z = (a0.z + a1.z + a2.z + a3.z) * dd + bv.z;
    o.w = (a0.w + a1.w + a2.w + a3.w) * dd + bv.w;
    ((float4*)hout)[(size_t)d * 32 + lane] = o;
}

// ---------------- head: out[N,2] = h @ Wh + bh ------------------------------
__global__ void __launch_bounds__(256) k_head(const float* __restrict__ h,
                                              const float* __restrict__ Wh,
                                              const float* __restrict__ bh,
                                              float* __restrict__ out) {
    const int wid  = (blockIdx.x * blockDim.x + threadIdx.x) >> 5;
    const int lane = threadIdx.x & 31;
    if (wid >= N_NODES) return;

    float4 v = ((const float4*)(h + (size_t)wid * 128))[lane];
    float4 w0 = *(const float4*)(Wh + lane * 8);
    float4 w1 = *(const float4*)(Wh + lane * 8 + 4);
    float p0 = v.x * w0.x + v.y * w0.z + v.z * w1.x + v.w * w1.z;
    float p1 = v.x * w0.y + v.y * w0.w + v.z * w1.y + v.w * w1.w;
#pragma unroll
    for (int off = 16; off; off >>= 1) {
        p0 += __shfl_xor_sync(0xFFFFFFFFu, p0, off);
        p1 += __shfl_xor_sync(0xFFFFFFFFu, p1, off);
    }
    if (lane == 0) {
        out[wid * 2 + 0] = p0 + bh[0];
        out[wid * 2 + 1] = p1 + bh[1];
    }
}

// ---------------- launch -----------------------------------------------------
extern "C" void kernel_launch(void* const* d_in, const int* in_sizes, int n_in,
                              void* d_out, int out_size) {
    const void*  ei = d_in[0];
    const float* x  = (const float*)d_in[1];
    const float* Wi = (const float*)d_in[2];
    const float* bi = (const float*)d_in[3];
    const float* W1 = (const float*)d_in[4];
    const float* b1 = (const float*)d_in[5];
    const float* W2 = (const float*)d_in[6];
    const float* b2 = (const float*)d_in[7];
    const float* Wh = (const float*)d_in[8];
    const float* bh = (const float*)d_in[9];
    float* out = (float*)d_out;

    float *h, *t;
    cudaGetSymbolAddress((void**)&h, d_h);
    cudaGetSymbolAddress((void**)&t, d_t);

    const int EB = (NE + 255) / 256;
    const int NB = (N_NODES + 255) / 256;
    const int GB = (N_NODES + 127) / 128;
    const int WB = (N_NODES + 7) / 8;
    const int WS1 = (128 * IN_DIM / 2 + 255) / 256;  // wsplit grids
    const int WS2 = (128 * HID / 2 + 255) / 256;

    // 1. edge dtype + CSR by destination + degree normalization
    k_detect<<<1, 1>>>((const int*)ei);
    k_zero_cnt<<<NB, 256>>>();
    k_convert_count<<<EB, 256>>>(ei);
    k_scan1<<<SCAN_B, 1024>>>();
    k_scan2<<<1, 128>>>();
    k_scan3<<<NB, 256>>>();
    k_fill<<<EB, 256>>>();

    // 2. node init: h = relu(x @ Wi + bi)
    k_wsplit<IN_DIM><<<WS1, 256>>>(Wi);
    k_gemm_tc<IN_DIM, true, true><<<GB, 256>>>(x, bi, h, N_NODES);

    // 3. GCN layer 1
    k_wsplit<HID><<<WS2, 256>>>(W1);
    k_gemm_tc<HID, false, false><<<GB, 256>>>(h, nullptr, t, N_NODES);
    k_aggregate<<<WB, 256>>>(t, b1, h);

    // 4. GCN layer 2
    k_wsplit<HID><<<WS2, 256>>>(W2);
    k_gemm_tc<HID, false, false><<<GB, 256>>>(h, nullptr, t, N_NODES);
    k_aggregate<<<WB, 256>>>(t, b2, h);

    // 5. head
    k_head<<<WB, 256>>>(h, Wh, bh, out);
}

// round 9
// speedup vs baseline: 1.0736x; 1.0736x over previous
#include <cuda_runtime.h>
#include <cuda_bf16.h>
#include <cuda_fp16.h>
#include <stdint.h>

#define N_NODES 100000
#define NE      1600000
#define IN_DIM  256
#define HID     128
#define SCAN_B  ((N_NODES + 1023) / 1024)   // 98 scan blocks

// ---------------- scratch (static device globals; no allocation) ------------
__device__ int    d_srcs[NE];      // CSR-permuted source indices (by dst)
__device__ int    d_cnt[N_NODES];
__device__ int    d_rowptr[N_NODES];
__device__ int    d_cursor[N_NODES];
__device__ float  d_dinv[N_NODES];
__device__ int    d_bsum[SCAN_B];
__device__ int    d_boff[SCAN_B];
__device__ float  d_h[(size_t)N_NODES * HID];
__device__ __half d_t[(size_t)N_NODES * HID];   // fp16 message tensor
__device__ int    g_is64;

// ---------------- helpers -----------------------------------------------------
__device__ __forceinline__ unsigned pack_bf16x2(float k_even, float k_odd) {
    unsigned r;
    asm("cvt.rn.bf16x2.f32 %0, %1, %2;" : "=r"(r) : "f"(k_odd), "f"(k_even));
    return r;
}
__device__ __forceinline__ void mma_bf16(float* c, unsigned a0, unsigned a1,
                                         unsigned a2, unsigned a3,
                                         unsigned b0, unsigned b1) {
    asm("mma.sync.aligned.m16n8k16.row.col.f32.bf16.bf16.f32 "
        "{%0,%1,%2,%3}, {%4,%5,%6,%7}, {%8,%9}, {%0,%1,%2,%3};"
        : "+f"(c[0]), "+f"(c[1]), "+f"(c[2]), "+f"(c[3])
        : "r"(a0), "r"(a1), "r"(a2), "r"(a3), "r"(b0), "r"(b1));
}

// ---------------- edge dtype detection ---------------------------------------
__global__ void k_detect(const int* __restrict__ w) {
    int ok = 1;
    for (int i = 0; i < 64; i++) {
        if (w[2 * i + 1] != 0) { ok = 0; break; }
    }
    g_is64 = ok;
}

__global__ void k_zero_cnt() {
    int i = blockIdx.x * blockDim.x + threadIdx.x;
    if (i < N_NODES) d_cnt[i] = 0;
}

__global__ void k_count(const void* __restrict__ ei) {
    int e = blockIdx.x * blockDim.x + threadIdx.x;
    if (e >= NE) return;
    int d;
    if (g_is64) d = (int)((const long long*)ei)[e + NE];
    else        d = ((const int*)ei)[e + NE];
    atomicAdd(&d_cnt[d], 1);
}

// ---------------- parallel 3-phase scan --------------------------------------
__global__ void __launch_bounds__(1024) k_scan1() {
    __shared__ int wsum[32];
    const int tid  = threadIdx.x;
    const int lane = tid & 31;
    const int w    = tid >> 5;
    const int gid  = blockIdx.x * 1024 + tid;

    int c = (gid < N_NODES) ? d_cnt[gid] : 0;
    int v = c;
#pragma unroll
    for (int o = 1; o < 32; o <<= 1) {
        int t = __shfl_up_sync(0xFFFFFFFFu, v, o);
        if (lane >= o) v += t;
    }
    if (lane == 31) wsum[w] = v;
    __syncthreads();
    if (w == 0) {
        int s = wsum[lane];
#pragma unroll
        for (int o = 1; o < 32; o <<= 1) {
            int t = __shfl_up_sync(0xFFFFFFFFu, s, o);
            if (lane >= o) s += t;
        }
        wsum[lane] = s;
    }
    __syncthreads();
    int excl = v - c + (w ? wsum[w - 1] : 0);
    if (gid < N_NODES) d_rowptr[gid] = excl;
    if (tid == 1023) d_bsum[blockIdx.x] = wsum[31];
}

__global__ void k_scan2() {
    __shared__ int s[128];
    const int t = threadIdx.x;
    s[t] = (t < SCAN_B) ? d_bsum[t] : 0;
    __syncthreads();
    for (int o = 1; o < 128; o <<= 1) {
        int v = (t >= o) ? s[t - o] : 0;
        __syncthreads();
        s[t] += v;
        __syncthreads();
    }
    if (t < SCAN_B) d_boff[t] = (t ? s[t - 1] : 0);
}

__global__ void k_scan3() {
    const int gid = blockIdx.x * blockDim.x + threadIdx.x;
    if (gid >= N_NODES) return;
    int rp = d_rowptr[gid] + d_boff[gid >> 10];
    d_rowptr[gid] = rp;
    d_cursor[gid] = rp;
    d_dinv[gid] = rsqrtf((float)(d_cnt[gid] + 1));  // +1 = self loop
}

__global__ void k_fill(const void* __restrict__ ei) {
    int e = blockIdx.x * blockDim.x + threadIdx.x;
    if (e >= NE) return;
    int s, d;
    if (g_is64) {
        const long long* p = (const long long*)ei;
        s = (int)p[e];
        d = (int)p[e + NE];
    } else {
        const int* p = (const int*)ei;
        s = p[e];
        d = p[e + NE];
    }
    int pos = atomicAdd(&d_cursor[d], 1);
    d_srcs[pos] = s;
}

// ---------------- tensor-core GEMM (round-6 config) --------------------------
// C[M,128] = act(A[M,K] @ W[K,128] + b), split-bf16 3-term compensation.
// 256 threads / 8 warps, tile 128x128, BK=32, smem stride PAD=20.
// HALF_OUT: store output as __half (message tensor t), else float.
#define PAD 20
template <int K, bool RELU, bool BIAS, bool HALF_OUT>
__global__ void __launch_bounds__(256) k_gemm_tc(const float* __restrict__ A,
                                                 const float* __restrict__ W,
                                                 const float* __restrict__ bias,
                                                 void* __restrict__ Cv, int M) {
    __shared__ unsigned sAhi[128][PAD];
    __shared__ unsigned sAlo[128][PAD];
    __shared__ unsigned sWhi[128][PAD];
    __shared__ unsigned sWlo[128][PAD];

    const int tid   = threadIdx.x;
    const int warp  = tid >> 5;
    const int lane  = tid & 31;
    const int g     = lane >> 2;
    const int tig   = lane & 3;
    const int mbase = warp * 16;
    const int row0  = blockIdx.x * 128;

    float acc[16][4];
#pragma unroll
    for (int nb = 0; nb < 16; nb++)
#pragma unroll
        for (int i = 0; i < 4; i++) acc[nb][i] = 0.f;

    for (int kc = 0; kc < K; kc += 32) {
        // ---- A tile: 128 rows x 32 k = 1024 float4 --------------------------
#pragma unroll
        for (int i = 0; i < 4; i++) {
            int idx = tid + i * 256;
            int r = idx >> 3, c4 = idx & 7;
            int grow = row0 + r;
            float4 v = make_float4(0.f, 0.f, 0.f, 0.f);
            if (grow < M)
                v = *(const float4*)(A + (size_t)grow * K + kc + c4 * 4);
            float hx = __bfloat162float(__float2bfloat16(v.x));
            float hy = __bfloat162float(__float2bfloat16(v.y));
            float hz = __bfloat162float(__float2bfloat16(v.z));
            float hw = __bfloat162float(__float2bfloat16(v.w));
            sAhi[r][c4 * 2 + 0] = pack_bf16x2(hx, hy);
            sAhi[r][c4 * 2 + 1] = pack_bf16x2(hz, hw);
            sAlo[r][c4 * 2 + 0] = pack_bf16x2(v.x - hx, v.y - hy);
            sAlo[r][c4 * 2 + 1] = pack_bf16x2(v.z - hz, v.w - hw);
        }
        // ---- W tile (transposed) --------------------------------------------
#pragma unroll
        for (int i = 0; i < 8; i++) {
            int idx = tid + i * 256;
            int n = idx & 127, kp = idx >> 7;
            float w0 = W[(size_t)(kc + 2 * kp)     * 128 + n];
            float w1 = W[(size_t)(kc + 2 * kp + 1) * 128 + n];
            float h0 = __bfloat162float(__float2bfloat16(w0));
            float h1 = __bfloat162float(__float2bfloat16(w1));
            sWhi[n][kp] = pack_bf16x2(h0, h1);
            sWlo[n][kp] = pack_bf16x2(w0 - h0, w1 - h1);
        }
        __syncthreads();

#pragma unroll
        for (int kk = 0; kk < 2; kk++) {
            const int kp = kk * 8 + tig;
            unsigned ah0 = sAhi[mbase + g][kp];
            unsigned ah1 = sAhi[mbase + g + 8][kp];
            unsigned ah2 = sAhi[mbase + g][kp + 4];
            unsigned ah3 = sAhi[mbase + g + 8][kp + 4];
            unsigned al0 = sAlo[mbase + g][kp];
            unsigned al1 = sAlo[mbase + g + 8][kp];
            unsigned al2 = sAlo[mbase + g][kp + 4];
            unsigned al3 = sAlo[mbase + g + 8][kp + 4];
#pragma unroll
            for (int nb = 0; nb < 16; nb++) {
                unsigned bh0 = sWhi[nb * 8 + g][kp];
                unsigned bh1 = sWhi[nb * 8 + g][kp + 4];
                unsigned bl0 = sWlo[nb * 8 + g][kp];
                unsigned bl1 = sWlo[nb * 8 + g][kp + 4];
                mma_bf16(acc[nb], ah0, ah1, ah2, ah3, bh0, bh1);  // hi*hi
                mma_bf16(acc[nb], ah0, ah1, ah2, ah3, bl0, bl1);  // hi*lo
                mma_bf16(acc[nb], al0, al1, al2, al3, bh0, bh1);  // lo*hi
            }
        }
        __syncthreads();
    }

    // ---- epilogue -----------------------------------------------------------
    const int r0 = row0 + mbase + g;
    const int r1 = r0 + 8;
#pragma unroll
    for (int nb = 0; nb < 16; nb++) {
        int col = nb * 8 + tig * 2;
        float b0 = 0.f, b1 = 0.f;
        if (BIAS) { b0 = bias[col]; b1 = bias[col + 1]; }
        float2 v0, v1;
        v0.x = acc[nb][0] + b0; v0.y = acc[nb][1] + b1;
        v1.x = acc[nb][2] + b0; v1.y = acc[nb][3] + b1;
        if (RELU) {
            v0.x = fmaxf(v0.x, 0.f); v0.y = fmaxf(v0.y, 0.f);
            v1.x = fmaxf(v1.x, 0.f); v1.y = fmaxf(v1.y, 0.f);
        }
        if (HALF_OUT) {
            __half* C = (__half*)Cv;
            if (r0 < M) *(__half2*)(C + (size_t)r0 * 128 + col) = __float22half2_rn(v0);
            if (r1 < M) *(__half2*)(C + (size_t)r1 * 128 + col) = __float22half2_rn(v1);
        } else {
            float* C = (float*)Cv;
            if (r0 < M) *(float2*)(C + (size_t)r0 * 128 + col) = v0;
            if (r1 < M) *(float2*)(C + (size_t)r1 * 128 + col) = v1;
        }
    }
}

// ---------------- GCN aggregate: warp per node, fp16 messages ---------------
__device__ __forceinline__ float4 load_t4(const __half* __restrict__ t,
                                          int node, int lane) {
    uint2 u = *(const uint2*)(t + (size_t)node * 128 + lane * 4);
    __half2 h0 = *(__half2*)&u.x;
    __half2 h1 = *(__half2*)&u.y;
    float2 f0 = __half22float2(h0);
    float2 f1 = __half22float2(h1);
    return make_float4(f0.x, f0.y, f1.x, f1.y);
}

__global__ void __launch_bounds__(256) k_aggregate(const __half* __restrict__ t,
                                                   const float* __restrict__ b,
                                                   float* __restrict__ hout) {
    const int wid  = (blockIdx.x * blockDim.x + threadIdx.x) >> 5;
    const int lane = threadIdx.x & 31;
    if (wid >= N_NODES) return;
    const int d = wid;

    const float dd = d_dinv[d];

    float4 a0 = load_t4(t, d, lane);   // self term
    a0.x *= dd; a0.y *= dd; a0.z *= dd; a0.w *= dd;
    float4 a1 = make_float4(0.f, 0.f, 0.f, 0.f);
    float4 a2 = make_float4(0.f, 0.f, 0.f, 0.f);
    float4 a3 = make_float4(0.f, 0.f, 0.f, 0.f);

    const int beg = d_rowptr[d];
    const int num = d_cnt[d];
    int j = 0;
    for (; j + 4 <= num; j += 4) {
        int s0 = d_srcs[beg + j];
        int s1 = d_srcs[beg + j + 1];
        int s2 = d_srcs[beg + j + 2];
        int s3 = d_srcs[beg + j + 3];
        float ds0 = d_dinv[s0], ds1 = d_dinv[s1];
        float ds2 = d_dinv[s2], ds3 = d_dinv[s3];
        float4 v0 = load_t4(t, s0, lane);
        float4 v1 = load_t4(t, s1, lane);
        float4 v2 = load_t4(t, s2, lane);
        float4 v3 = load_t4(t, s3, lane);
        a0.x += v0.x * ds0; a0.y += v0.y * ds0; a0.z += v0.z * ds0; a0.w += v0.w * ds0;
        a1.x += v1.x * ds1; a1.y += v1.y * ds1; a1.z += v1.z * ds1; a1.w += v1.w * ds1;
        a2.x += v2.x * ds2; a2.y += v2.y * ds2; a2.z += v2.z * ds2; a2.w += v2.w * ds2;
        a3.x += v3.x * ds3; a3.y += v3.y * ds3; a3.z += v3.z * ds3; a3.w += v3.w * ds3;
    }
    for (; j < num; j++) {
        int s = d_srcs[beg + j];
        float ds = d_dinv[s];
        float4 v = load_t4(t, s, lane);
        a0.x += v.x * ds; a0.y += v.y * ds; a0.z += v.z * ds; a0.w += v.w * ds;
    }

    float4 bv = ((const float4*)b)[lane];
    float4 o;
    o.x = (a0.x + a1.x + a2.x + a3.x) * dd + bv.x;
    o.y = (a0.y + a1.y + a2.y + a3.y) * dd + bv.y;
    o.z = (a0.z + a1.z + a2.z + a3.z) * dd + bv.z;
    o.w = (a0.w + a1.w + a2.w + a3.w) * dd + bv.w;
    ((float4*)hout)[(size_t)d * 32 + lane] = o;
}

// ---------------- head: out[N,2] = h @ Wh + bh ------------------------------
__global__ void __launch_bounds__(256) k_head(const float* __restrict__ h,
                                              const float* __restrict__ Wh,
                                              const float* __restrict__ bh,
                                              float* __restrict__ out) {
    const int wid  = (blockIdx.x * blockDim.x + threadIdx.x) >> 5;
    const int lane = threadIdx.x & 31;
    if (wid >= N_NODES) return;

    float4 v = ((const float4*)(h + (size_t)wid * 128))[lane];
    float4 w0 = *(const float4*)(Wh + lane * 8);
    float4 w1 = *(const float4*)(Wh + lane * 8 + 4);
    float p0 = v.x * w0.x + v.y * w0.z + v.z * w1.x + v.w * w1.z;
    float p1 = v.x * w0.y + v.y * w0.w + v.z * w1.y + v.w * w1.w;
#pragma unroll
    for (int off = 16; off; off >>= 1) {
        p0 += __shfl_xor_sync(0xFFFFFFFFu, p0, off);
        p1 += __shfl_xor_sync(0xFFFFFFFFu, p1, off);
    }
    if (lane == 0) {
        out[wid * 2 + 0] = p0 + bh[0];
        out[wid * 2 + 1] = p1 + bh[1];
    }
}

// ---------------- launch -----------------------------------------------------
extern "C" void kernel_launch(void* const* d_in, const int* in_sizes, int n_in,
                              void* d_out, int out_size) {
    const void*  ei = d_in[0];
    const float* x  = (const float*)d_in[1];
    const float* Wi = (const float*)d_in[2];
    const float* bi = (const float*)d_in[3];
    const float* W1 = (const float*)d_in[4];
    const float* b1 = (const float*)d_in[5];
    const float* W2 = (const float*)d_in[6];
    const float* b2 = (const float*)d_in[7];
    const float* Wh = (const float*)d_in[8];
    const float* bh = (const float*)d_in[9];
    float* out = (float*)d_out;

    float  *h;
    __half *t;
    cudaGetSymbolAddress((void**)&h, d_h);
    cudaGetSymbolAddress((void**)&t, d_t);

    const int EB = (NE + 255) / 256;
    const int NB = (N_NODES + 255) / 256;
    const int GB = (N_NODES + 127) / 128;
    const int WB = (N_NODES + 7) / 8;

    // 1. edge dtype + CSR by destination + degree normalization
    k_detect<<<1, 1>>>((const int*)ei);
    k_zero_cnt<<<NB, 256>>>();
    k_count<<<EB, 256>>>(ei);
    k_scan1<<<SCAN_B, 1024>>>();
    k_scan2<<<1, 128>>>();
    k_scan3<<<NB, 256>>>();
    k_fill<<<EB, 256>>>(ei);

    // 2. node init: h = relu(x @ Wi + bi)  (fp32 out)
    k_gemm_tc<IN_DIM, true, true, false><<<GB, 256>>>(x, Wi, bi, h, N_NODES);

    // 3. GCN layer 1: t = h @ W1 (fp16 out); h = aggregate(t) + b1
    k_gemm_tc<HID, false, false, true><<<GB, 256>>>(h, W1, nullptr, t, N_NODES);
    k_aggregate<<<WB, 256>>>(t, b1, h);

    // 4. GCN layer 2
    k_gemm_tc<HID, false, false, true><<<GB, 256>>>(h, W2, nullptr, t, N_NODES);
    k_aggregate<<<WB, 256>>>(t, b2, h);

    // 5. head
    k_head<<<WB, 256>>>(h, Wh, bh, out);
}

// round 10
// speedup vs baseline: 1.2576x; 1.1714x over previous
#include <cuda_runtime.h>
#include <cuda_bf16.h>
#include <stdint.h>

#define N_NODES 100000
#define NE      1600000
#define IN_DIM  256
#define HID     128
#define SCAN_B  ((N_NODES + 1023) / 1024)   // 98 scan blocks

// ---------------- scratch (static device globals; no allocation) ------------
__device__ int   d_src32[NE];
__device__ int   d_dst32[NE];
__device__ int   d_srcs[NE];       // CSR-permuted source indices (by dst)
__device__ int   d_cnt[N_NODES];
__device__ int   d_rowptr[N_NODES];
__device__ int   d_cursor[N_NODES];
__device__ float d_dinv[N_NODES];
__device__ int   d_bsum[SCAN_B];
__device__ int   d_boff[SCAN_B];
__device__ float d_h[(size_t)N_NODES * HID];
__device__ float d_t[(size_t)N_NODES * HID];
__device__ float d_w2h[HID * 2];   // folded W2 @ Wh  [128,2]
__device__ float d_bh2[2];         // folded b2 @ Wh + bh
__device__ int   g_is64;

// ---------------- helpers -----------------------------------------------------
__device__ __forceinline__ unsigned pack_bf16x2(float k_even, float k_odd) {
    unsigned r;
    asm("cvt.rn.bf16x2.f32 %0, %1, %2;" : "=r"(r) : "f"(k_odd), "f"(k_even));
    return r;
}
__device__ __forceinline__ void mma_bf16(float* c, unsigned a0, unsigned a1,
                                         unsigned a2, unsigned a3,
                                         unsigned b0, unsigned b1) {
    asm("mma.sync.aligned.m16n8k16.row.col.f32.bf16.bf16.f32 "
        "{%0,%1,%2,%3}, {%4,%5,%6,%7}, {%8,%9}, {%0,%1,%2,%3};"
        : "+f"(c[0]), "+f"(c[1]), "+f"(c[2]), "+f"(c[3])
        : "r"(a0), "r"(a1), "r"(a2), "r"(a3), "r"(b0), "r"(b1));
}

// ---------------- edge dtype detection + conversion + count ------------------
__global__ void k_detect(const int* __restrict__ w) {
    int ok = 1;
    for (int i = 0; i < 64; i++) {
        if (w[2 * i + 1] != 0) { ok = 0; break; }
    }
    g_is64 = ok;
}

__global__ void k_zero_cnt() {
    int i = blockIdx.x * blockDim.x + threadIdx.x;
    if (i < N_NODES) d_cnt[i] = 0;
}

__global__ void k_convert_count(const void* __restrict__ ei) {
    int e = blockIdx.x * blockDim.x + threadIdx.x;
    if (e >= NE) return;
    int s, d;
    if (g_is64) {
        const long long* p = (const long long*)ei;
        s = (int)p[e];
        d = (int)p[e + NE];
    } else {
        const int* p = (const int*)ei;
        s = p[e];
        d = p[e + NE];
    }
    d_src32[e] = s;
    d_dst32[e] = d;
    atomicAdd(&d_cnt[d], 1);
}

// ---------------- parallel 3-phase scan --------------------------------------
__global__ void __launch_bounds__(1024) k_scan1() {
    __shared__ int wsum[32];
    const int tid  = threadIdx.x;
    const int lane = tid & 31;
    const int w    = tid >> 5;
    const int gid  = blockIdx.x * 1024 + tid;

    int c = (gid < N_NODES) ? d_cnt[gid] : 0;
    int v = c;
#pragma unroll
    for (int o = 1; o < 32; o <<= 1) {
        int t = __shfl_up_sync(0xFFFFFFFFu, v, o);
        if (lane >= o) v += t;
    }
    if (lane == 31) wsum[w] = v;
    __syncthreads();
    if (w == 0) {
        int s = wsum[lane];
#pragma unroll
        for (int o = 1; o < 32; o <<= 1) {
            int t = __shfl_up_sync(0xFFFFFFFFu, s, o);
            if (lane >= o) s += t;
        }
        wsum[lane] = s;
    }
    __syncthreads();
    int excl = v - c + (w ? wsum[w - 1] : 0);
    if (gid < N_NODES) d_rowptr[gid] = excl;
    if (tid == 1023) d_bsum[blockIdx.x] = wsum[31];
}

__global__ void k_scan2() {
    __shared__ int s[128];
    const int t = threadIdx.x;
    s[t] = (t < SCAN_B) ? d_bsum[t] : 0;
    __syncthreads();
    for (int o = 1; o < 128; o <<= 1) {
        int v = (t >= o) ? s[t - o] : 0;
        __syncthreads();
        s[t] += v;
        __syncthreads();
    }
    if (t < SCAN_B) d_boff[t] = (t ? s[t - 1] : 0);
}

__global__ void k_scan3() {
    const int gid = blockIdx.x * blockDim.x + threadIdx.x;
    if (gid >= N_NODES) return;
    int rp = d_rowptr[gid] + d_boff[gid >> 10];
    d_rowptr[gid] = rp;
    d_cursor[gid] = rp;
    d_dinv[gid] = rsqrtf((float)(d_cnt[gid] + 1));  // +1 = self loop
}

__global__ void k_fill() {
    int e = blockIdx.x * blockDim.x + threadIdx.x;
    if (e >= NE) return;
    int dd = d_dst32[e];
    int pos = atomicAdd(&d_cursor[dd], 1);
    d_srcs[pos] = d_src32[e];
}

// ---------------- weight folding: W2h = W2 @ Wh, bh2 = b2 @ Wh + bh ---------
__global__ void k_fold(const float* __restrict__ W2,
                       const float* __restrict__ Wh,
                       const float* __restrict__ b2,
                       const float* __restrict__ bh) {
    const int i = threadIdx.x;           // 256 threads
    const int k = i >> 1, j = i & 1;
    float s = 0.f;
#pragma unroll 8
    for (int m = 0; m < HID; m++)
        s += W2[(size_t)k * HID + m] * Wh[m * 2 + j];
    d_w2h[k * 2 + j] = s;
    if (k == 0) {
        float t = bh[j];
        for (int m = 0; m < HID; m++) t += b2[m] * Wh[m * 2 + j];
        d_bh2[j] = t;
    }
}

// ---------------- tensor-core GEMM (round-6 config) --------------------------
// C[M,128] = act(A[M,K] @ W[K,128] + b), split-bf16 3-term compensation.
#define PAD 20
template <int K, bool RELU, bool BIAS>
__global__ void __launch_bounds__(256) k_gemm_tc(const float* __restrict__ A,
                                                 const float* __restrict__ W,
                                                 const float* __restrict__ bias,
                                                 float* __restrict__ C, int M) {
    __shared__ unsigned sAhi[128][PAD];
    __shared__ unsigned sAlo[128][PAD];
    __shared__ unsigned sWhi[128][PAD];
    __shared__ unsigned sWlo[128][PAD];

    const int tid   = threadIdx.x;
    const int warp  = tid >> 5;
    const int lane  = tid & 31;
    const int g     = lane >> 2;
    const int tig   = lane & 3;
    const int mbase = warp * 16;
    const int row0  = blockIdx.x * 128;

    float acc[16][4];
#pragma unroll
    for (int nb = 0; nb < 16; nb++)
#pragma unroll
        for (int i = 0; i < 4; i++) acc[nb][i] = 0.f;

    for (int kc = 0; kc < K; kc += 32) {
#pragma unroll
        for (int i = 0; i < 4; i++) {
            int idx = tid + i * 256;
            int r = idx >> 3, c4 = idx & 7;
            int grow = row0 + r;
            float4 v = make_float4(0.f, 0.f, 0.f, 0.f);
            if (grow < M)
                v = *(const float4*)(A + (size_t)grow * K + kc + c4 * 4);
            float hx = __bfloat162float(__float2bfloat16(v.x));
            float hy = __bfloat162float(__float2bfloat16(v.y));
            float hz = __bfloat162float(__float2bfloat16(v.z));
            float hw = __bfloat162float(__float2bfloat16(v.w));
            sAhi[r][c4 * 2 + 0] = pack_bf16x2(hx, hy);
            sAhi[r][c4 * 2 + 1] = pack_bf16x2(hz, hw);
            sAlo[r][c4 * 2 + 0] = pack_bf16x2(v.x - hx, v.y - hy);
            sAlo[r][c4 * 2 + 1] = pack_bf16x2(v.z - hz, v.w - hw);
        }
#pragma unroll
        for (int i = 0; i < 8; i++) {
            int idx = tid + i * 256;
            int n = idx & 127, kp = idx >> 7;
            float w0 = W[(size_t)(kc + 2 * kp)     * 128 + n];
            float w1 = W[(size_t)(kc + 2 * kp + 1) * 128 + n];
            float h0 = __bfloat162float(__float2bfloat16(w0));
            float h1 = __bfloat162float(__float2bfloat16(w1));
            sWhi[n][kp] = pack_bf16x2(h0, h1);
            sWlo[n][kp] = pack_bf16x2(w0 - h0, w1 - h1);
        }
        __syncthreads();

#pragma unroll
        for (int kk = 0; kk < 2; kk++) {
            const int kp = kk * 8 + tig;
            unsigned ah0 = sAhi[mbase + g][kp];
            unsigned ah1 = sAhi[mbase + g + 8][kp];
            unsigned ah2 = sAhi[mbase + g][kp + 4];
            unsigned ah3 = sAhi[mbase + g + 8][kp + 4];
            unsigned al0 = sAlo[mbase + g][kp];
            unsigned al1 = sAlo[mbase + g + 8][kp];
            unsigned al2 = sAlo[mbase + g][kp + 4];
            unsigned al3 = sAlo[mbase + g + 8][kp + 4];
#pragma unroll
            for (int nb = 0; nb < 16; nb++) {
                unsigned bh0 = sWhi[nb * 8 + g][kp];
                unsigned bh1 = sWhi[nb * 8 + g][kp + 4];
                unsigned bl0 = sWlo[nb * 8 + g][kp];
                unsigned bl1 = sWlo[nb * 8 + g][kp + 4];
                mma_bf16(acc[nb], ah0, ah1, ah2, ah3, bh0, bh1);  // hi*hi
                mma_bf16(acc[nb], ah0, ah1, ah2, ah3, bl0, bl1);  // hi*lo
                mma_bf16(acc[nb], al0, al1, al2, al3, bh0, bh1);  // lo*hi
            }
        }
        __syncthreads();
    }

    const int r0 = row0 + mbase + g;
    const int r1 = r0 + 8;
#pragma unroll
    for (int nb = 0; nb < 16; nb++) {
        int col = nb * 8 + tig * 2;
        float b0 = 0.f, b1 = 0.f;
        if (BIAS) { b0 = bias[col]; b1 = bias[col + 1]; }
        float2 v0, v1;
        v0.x = acc[nb][0] + b0; v0.y = acc[nb][1] + b1;
        v1.x = acc[nb][2] + b0; v1.y = acc[nb][3] + b1;
        if (RELU) {
            v0.x = fmaxf(v0.x, 0.f); v0.y = fmaxf(v0.y, 0.f);
            v1.x = fmaxf(v1.x, 0.f); v1.y = fmaxf(v1.y, 0.f);
        }
        if (r0 < M) *(float2*)(C + (size_t)r0 * 128 + col) = v0;
        if (r1 < M) *(float2*)(C + (size_t)r1 * 128 + col) = v1;
    }
}

// ---------------- GCN aggregate (layer 1): warp per destination node --------
__global__ void __launch_bounds__(256) k_aggregate(const float* __restrict__ t,
                                                   const float* __restrict__ b,
                                                   float* __restrict__ hout) {
    const int wid  = (blockIdx.x * blockDim.x + threadIdx.x) >> 5;
    const int lane = threadIdx.x & 31;
    if (wid >= N_NODES) return;
    const int d = wid;

    const float4* t4 = (const float4*)t;
    const float dd = d_dinv[d];

    float4 a0 = t4[d * 32 + lane];   // self term
    a0.x *= dd; a0.y *= dd; a0.z *= dd; a0.w *= dd;
    float4 a1 = make_float4(0.f, 0.f, 0.f, 0.f);

    const int beg = d_rowptr[d];
    const int num = d_cnt[d];
    int j = 0;
    for (; j + 2 <= num; j += 2) {
        int s0 = d_srcs[beg + j];
        int s1 = d_srcs[beg + j + 1];
        float ds0 = d_dinv[s0];
        float ds1 = d_dinv[s1];
        float4 v0 = t4[s0 * 32 + lane];
        float4 v1 = t4[s1 * 32 + lane];
        a0.x += v0.x * ds0; a0.y += v0.y * ds0;
        a0.z += v0.z * ds0; a0.w += v0.w * ds0;
        a1.x += v1.x * ds1; a1.y += v1.y * ds1;
        a1.z += v1.z * ds1; a1.w += v1.w * ds1;
    }
    if (j < num) {
        int s = d_srcs[beg + j];
        float ds = d_dinv[s];
        float4 v = t4[s * 32 + lane];
        a0.x += v.x * ds; a0.y += v.y * ds;
        a0.z += v.z * ds; a0.w += v.w * ds;
    }

    float4 bv = ((const float4*)b)[lane];
    float4 o;
    o.x = (a0.x + a1.x) * dd + bv.x;
    o.y = (a0.y + a1.y) * dd + bv.y;
    o.z = (a0.z + a1.z) * dd + bv.z;
    o.w = (a0.w + a1.w) * dd + bv.w;
    ((float4*)hout)[(size_t)d * 32 + lane] = o;
}

// ---------------- fused aggregate + head ------------------------------------
// out[d] = (P·h1)[d] @ W2h + bh2   (layer-2 GEMM folded into the 128x2 head)
__global__ void __launch_bounds__(256) k_agg_head(const float* __restrict__ h1,
                                                  float* __restrict__ out) {
    const int wid  = (blockIdx.x * blockDim.x + threadIdx.x) >> 5;
    const int lane = threadIdx.x & 31;
    if (wid >= N_NODES) return;
    const int d = wid;

    const float4* t4 = (const float4*)h1;
    const float dd = d_dinv[d];

    float4 a0 = t4[d * 32 + lane];   // self term
    a0.x *= dd; a0.y *= dd; a0.z *= dd; a0.w *= dd;
    float4 a1 = make_float4(0.f, 0.f, 0.f, 0.f);

    const int beg = d_rowptr[d];
    const int num = d_cnt[d];
    int j = 0;
    for (; j + 2 <= num; j += 2) {
        int s0 = d_srcs[beg + j];
        int s1 = d_srcs[beg + j + 1];
        float ds0 = d_dinv[s0];
        float ds1 = d_dinv[s1];
        float4 v0 = t4[s0 * 32 + lane];
        float4 v1 = t4[s1 * 32 + lane];
        a0.x += v0.x * ds0; a0.y += v0.y * ds0;
        a0.z += v0.z * ds0; a0.w += v0.w * ds0;
        a1.x += v1.x * ds1; a1.y += v1.y * ds1;
        a1.z += v1.z * ds1; a1.w += v1.w * ds1;
    }
    if (j < num) {
        int s = d_srcs[beg + j];
        float ds = d_dinv[s];
        float4 v = t4[s * 32 + lane];
        a0.x += v.x * ds; a0.y += v.y * ds;
        a0.z += v.z * ds; a0.w += v.w * ds;
    }

    float4 a;
    a.x = (a0.x + a1.x) * dd;
    a.y = (a0.y + a1.y) * dd;
    a.z = (a0.z + a1.z) * dd;
    a.w = (a0.w + a1.w) * dd;

    // dot with folded 128x2 weight (row-major [f][2]; lane covers f=lane*4..+3)
    float4 w0 = *(const float4*)(d_w2h + lane * 8);
    float4 w1 = *(const float4*)(d_w2h + lane * 8 + 4);
    float p0 = a.x * w0.x + a.y * w0.z + a.z * w1.x + a.w * w1.z;
    float p1 = a.x * w0.y + a.y * w0.w + a.z * w1.y + a.w * w1.w;
#pragma unroll
    for (int off = 16; off; off >>= 1) {
        p0 += __shfl_xor_sync(0xFFFFFFFFu, p0, off);
        p1 += __shfl_xor_sync(0xFFFFFFFFu, p1, off);
    }
    if (lane == 0) {
        out[d * 2 + 0] = p0 + d_bh2[0];
        out[d * 2 + 1] = p1 + d_bh2[1];
    }
}

// ---------------- launch -----------------------------------------------------
extern "C" void kernel_launch(void* const* d_in, const int* in_sizes, int n_in,
                              void* d_out, int out_size) {
    const void*  ei = d_in[0];
    const float* x  = (const float*)d_in[1];
    const float* Wi = (const float*)d_in[2];
    const float* bi = (const float*)d_in[3];
    const float* W1 = (const float*)d_in[4];
    const float* b1 = (const float*)d_in[5];
    const float* W2 = (const float*)d_in[6];
    const float* b2 = (const float*)d_in[7];
    const float* Wh = (const float*)d_in[8];
    const float* bh = (const float*)d_in[9];
    float* out = (float*)d_out;

    float *h, *t;
    cudaGetSymbolAddress((void**)&h, d_h);
    cudaGetSymbolAddress((void**)&t, d_t);

    const int EB = (NE + 255) / 256;
    const int NB = (N_NODES + 255) / 256;
    const int GB = (N_NODES + 127) / 128;
    const int WB = (N_NODES + 7) / 8;

    // Launch order puts the big GEMM at index 3 (ncu's capture slot).
    k_detect<<<1, 1>>>((const int*)ei);                               // 0
    k_zero_cnt<<<NB, 256>>>();                                        // 1
    k_convert_count<<<EB, 256>>>(ei);                                 // 2
    k_gemm_tc<IN_DIM, true, true><<<GB, 256>>>(x, Wi, bi, h, N_NODES); // 3 <- profiled
    k_scan1<<<SCAN_B, 1024>>>();                                      // 4
    k_scan2<<<1, 128>>>();                                            // 5
    k_scan3<<<NB, 256>>>();                                           // 6
    k_fill<<<EB, 256>>>();                                            // 7
    k_fold<<<1, 256>>>(W2, Wh, b2, bh);                               // 8

    // layer 1: t = h @ W1 ; h = P·t + b1
    k_gemm_tc<HID, false, false><<<GB, 256>>>(h, W1, nullptr, t, N_NODES);
    k_aggregate<<<WB, 256>>>(t, b1, h);

    // layer 2 + head fused: out = (P·h) @ (W2@Wh) + (b2@Wh + bh)
    k_agg_head<<<WB, 256>>>(h, out);
}